// round 17
// baseline (speedup 1.0000x reference)
#include <cuda_runtime.h>

// Problem constants
#define B_  256
#define T_  1024
#define I_  3
#define H_  128
#define O_  3

// ---------------------------------------------------------------------------
// Fast tanh: tanh(x) = 1 - 2/(1 + e^{2x}) via ex2.approx + rcp.approx.
// Limits are exact without clamping. Measured end-to-end rel err ~5e-7.
// ---------------------------------------------------------------------------
__device__ __forceinline__ float fast_tanh(float x) {
    float e;
    asm("ex2.approx.f32 %0, %1;" : "=f"(e) : "f"(x * 2.885390081777927f));
    float rd;
    asm("rcp.approx.f32 %0, %1;" : "=f"(rd) : "f"(1.0f + e));
    return fmaf(-2.0f, rd, 1.0f);
}

// ---------------------------------------------------------------------------
// Recurrent kernel: EXACT R12 configuration (best measured: ~369us).
// One block per batch, one thread per hidden unit, W_hh row in 128 regs,
// double-buffered h in smem, one barrier per step, x prefetch, input-proj
// seeding chain 0, anti-phase skew for second-slot blocks.
// ---------------------------------------------------------------------------
__global__ void __launch_bounds__(H_, 2)
rnn_recurrent_kernel(const float* __restrict__ inputs,   // [B, T, I]
                     const float* __restrict__ W_ih,     // [H, I]
                     const float* __restrict__ W_hh,     // [H, H]
                     const float* __restrict__ b_ih,     // [H]
                     const float* __restrict__ b_hh,     // [H]
                     const float* __restrict__ h0,       // [1, H]
                     float* __restrict__ hiddens)        // [B, T, H]
{
    const int b = blockIdx.x;
    const int j = threadIdx.x;

    __shared__ float hbuf[2][H_];

    float w[H_];
    const float4* wrow = reinterpret_cast<const float4*>(W_hh + j * H_);
#pragma unroll
    for (int kk = 0; kk < H_ / 4; ++kk) {
        float4 v = wrow[kk];
        w[4 * kk + 0] = v.x;
        w[4 * kk + 1] = v.y;
        w[4 * kk + 2] = v.z;
        w[4 * kk + 3] = v.w;
    }

    const float wi0  = W_ih[j * I_ + 0];
    const float wi1  = W_ih[j * I_ + 1];
    const float wi2  = W_ih[j * I_ + 2];
    const float bias = b_ih[j] + b_hh[j];

    hbuf[0][j] = h0[j];

    // Anti-phase-lock skew for second-slot blocks
    if (b >= 148) {
        float d = bias * 1e-30f;
#pragma unroll 1
        for (int i = 0; i < 75; ++i)
            d = fmaf(d, 0.999f, 1e-30f);
        if (d > 1e10f) hbuf[0][0] = d;   // never taken
    }
    __syncthreads();

    const float* inb  = inputs + (size_t)b * T_ * I_;
    float*       hout = hiddens + (size_t)b * T_ * H_;

    float x0 = inb[0], x1 = inb[1], x2 = inb[2];

    int cur = 0;
#pragma unroll 1
    for (int t = 0; t < T_; ++t) {
        float a0 = fmaf(x0, wi0, fmaf(x1, wi1, fmaf(x2, wi2, bias)));
        float a1 = 0.f, a2 = 0.f, a3 = 0.f;

        {
            const int tn = (t + 1 < T_) ? (t + 1) : (T_ - 1);
            const float* nx = inb + tn * I_;
            x0 = nx[0]; x1 = nx[1]; x2 = nx[2];
        }

        const float4* h4 = reinterpret_cast<const float4*>(hbuf[cur]);
#pragma unroll
        for (int kk = 0; kk < H_ / 4; ++kk) {
            float4 hv = h4[kk];
            a0 = fmaf(hv.x, w[4 * kk + 0], a0);
            a1 = fmaf(hv.y, w[4 * kk + 1], a1);
            a2 = fmaf(hv.z, w[4 * kk + 2], a2);
            a3 = fmaf(hv.w, w[4 * kk + 3], a3);
        }
        const float acc = (a0 + a1) + (a2 + a3);

        const float hn = fast_tanh(acc);
        const int nxt = cur ^ 1;
        hbuf[nxt][j] = hn;
        hout[t * H_ + j] = hn;
        cur = nxt;
        __syncthreads();
    }
}

// ---------------------------------------------------------------------------
// Output projection v3: smem-staged, shuffle-free.
// Block = 256 threads, 64 rows.
//  Stage 1: stream 64x128 floats into padded smem (fully coalesced float4,
//           8 outstanding loads per thread -> high MLP).
//  Stage 2: 192 threads each compute one (row, o) dot of length 128 from
//           smem (h and W_out both in smem), 4 accumulators for ILP.
//  Stage 3: results staged in smem, written as one coalesced 768B block.
// Row padding 132 floats (33 float4): bank phase row*33 mod 32 distinct.
// ---------------------------------------------------------------------------
#define OP_THREADS 256
#define OP_ROWS 64
#define OP_PAD  132   // floats per padded row (33 float4)

__global__ void __launch_bounds__(OP_THREADS, 2)
rnn_outproj_kernel(const float* __restrict__ hiddens, // [B*T, H]
                   const float* __restrict__ W_out,   // [O, H]
                   const float* __restrict__ b_out,   // [O]
                   float* __restrict__ out)           // [B*T, O]
{
    __shared__ float sh[OP_ROWS * OP_PAD];     // 64 padded rows, 33.8KB
    __shared__ float sw[O_ * H_];              // W_out copy, 1.5KB
    __shared__ float so[OP_ROWS * O_];         // staged outputs, 768B

    const int tid = threadIdx.x;
    const size_t rowbase = (size_t)blockIdx.x * OP_ROWS;

    // Load W_out into smem (96 float4)
    if (tid < (O_ * H_) / 4) {
        reinterpret_cast<float4*>(sw)[tid] =
            reinterpret_cast<const float4*>(W_out)[tid];
    }

    // Stage 1: coalesced streaming load of 64 rows (2048 float4)
    const float4* src = reinterpret_cast<const float4*>(hiddens + rowbase * H_);
#pragma unroll
    for (int k = 0; k < (OP_ROWS * H_ / 4) / OP_THREADS; ++k) {
        const int idx = k * OP_THREADS + tid;       // global float4 index
        const int row = idx >> 5;                   // /32 float4 per row
        const int c4  = idx & 31;
        const float4 v = src[idx];
        *reinterpret_cast<float4*>(&sh[row * OP_PAD + c4 * 4]) = v;
    }
    __syncthreads();

    // Stage 2: 192 threads: thread = row*3 + o
    if (tid < OP_ROWS * O_) {
        const int row = tid / O_;
        const int o   = tid - row * O_;

        const float4* hp = reinterpret_cast<const float4*>(&sh[row * OP_PAD]);
        const float4* wp = reinterpret_cast<const float4*>(&sw[o * H_]);

        float s0 = 0.f, s1 = 0.f, s2 = 0.f, s3 = 0.f;
#pragma unroll
        for (int k4 = 0; k4 < H_ / 4; k4 += 4) {
            const float4 h0v = hp[k4 + 0], w0v = wp[k4 + 0];
            const float4 h1v = hp[k4 + 1], w1v = wp[k4 + 1];
            const float4 h2v = hp[k4 + 2], w2v = wp[k4 + 2];
            const float4 h3v = hp[k4 + 3], w3v = wp[k4 + 3];
            s0 = fmaf(h0v.x, w0v.x, s0); s0 = fmaf(h0v.y, w0v.y, s0);
            s0 = fmaf(h0v.z, w0v.z, s0); s0 = fmaf(h0v.w, w0v.w, s0);
            s1 = fmaf(h1v.x, w1v.x, s1); s1 = fmaf(h1v.y, w1v.y, s1);
            s1 = fmaf(h1v.z, w1v.z, s1); s1 = fmaf(h1v.w, w1v.w, s1);
            s2 = fmaf(h2v.x, w2v.x, s2); s2 = fmaf(h2v.y, w2v.y, s2);
            s2 = fmaf(h2v.z, w2v.z, s2); s2 = fmaf(h2v.w, w2v.w, s2);
            s3 = fmaf(h3v.x, w3v.x, s3); s3 = fmaf(h3v.y, w3v.y, s3);
            s3 = fmaf(h3v.z, w3v.z, s3); s3 = fmaf(h3v.w, w3v.w, s3);
        }
        so[tid] = ((s0 + s1) + (s2 + s3)) + b_out[o];
    }
    __syncthreads();

    // Stage 3: coalesced output write (192 floats = 768B)
    if (tid < OP_ROWS * O_) {
        out[rowbase * O_ + tid] = so[tid];
    }
}

// ---------------------------------------------------------------------------
// kernel_launch
// ---------------------------------------------------------------------------
extern "C" void kernel_launch(void* const* d_in, const int* in_sizes, int n_in,
                              void* d_out, int out_size)
{
    const float* inputs = (const float*)d_in[0];
    const float* W_ih   = (const float*)d_in[1];
    const float* W_hh   = (const float*)d_in[2];
    const float* b_ih   = (const float*)d_in[3];
    const float* b_hh   = (const float*)d_in[4];
    const float* h0     = (const float*)d_in[5];
    const float* W_out  = (const float*)d_in[6];
    const float* b_out  = (const float*)d_in[7];

    float* out     = (float*)d_out;                        // [B,T,O]
    float* hiddens = (float*)d_out + (size_t)B_ * T_ * O_; // [B,T,H]

    rnn_recurrent_kernel<<<B_, H_>>>(inputs, W_ih, W_hh, b_ih, b_hh, h0, hiddens);

    const int rows   = B_ * T_;               // 262144
    const int blocks = rows / OP_ROWS;        // 4096 (exact)
    rnn_outproj_kernel<<<blocks, OP_THREADS>>>(hiddens, W_out, b_out, out);
}